// round 10
// baseline (speedup 1.0000x reference)
#include <cuda_runtime.h>
#include <cstdint>

#define H 128
#define W 128
#define NS 8
#define TY 16
#define SROWS (TY + 8)    // 24
#define SCOLS 140         // multiple of 4; window index max 135 < 140

typedef unsigned long long u64;

// In-place packed FMA: acc = a*b + acc (acc stays pinned in one pair).
__device__ __forceinline__ void fma2(u64& acc, u64 a, u64 b) {
    asm("fma.rn.f32x2 %0, %1, %2, %0;" : "+l"(acc) : "l"(a), "l"(b));
}
__device__ __forceinline__ u64 pk(float lo, float hi) {
    u64 r; asm("mov.b64 %0, {%1, %2};" : "=l"(r) : "f"(lo), "f"(hi)); return r;
}
__device__ __forceinline__ float hadd(u64 v) {
    float a, b; asm("mov.b64 {%0, %1}, %2;" : "=f"(a), "=f"(b) : "l"(v));
    return a + b;
}

__global__ void __launch_bounds__(128, 4)
shifted_conv_kernel(const float* __restrict__ tens,
                    const float* __restrict__ filters,
                    const int* __restrict__ shifts,
                    float* __restrict__ out)
{
    // 4 copies shifted by 0..3 elements: s_t[c][r][j] = x_pad[r][j + c]
    __shared__ __align__(16) float s_t[4][SROWS][SCOLS];
    __shared__ __align__(16) float s_f[NS][5][8];   // f0..f4,0,0,0 per row
    __shared__ int s_sh[NS * 2];

    const int n    = blockIdx.x;        // 0..255 (B*C)
    const int y0   = blockIdx.y * TY;   // 0..112 step 16
    const int tid  = threadIdx.x;
    const int lane = tid & 31;
    const int wrp  = tid >> 5;

    // Stage filters padded to 8 per row (zeros beyond tap 4)
    for (int i = tid; i < NS * 5 * 8; i += 128) {
        int s = i / 40, rem = i - s * 40, fr = rem >> 3, fc = rem & 7;
        s_f[s][fr][fc] = (fc < 5) ? filters[s * 25 + fr * 5 + fc] : 0.0f;
    }
    if (tid < NS * 2) s_sh[tid] = shifts[tid];

    // Stage input strip once into 4 shifted copies (zero-padded OOB)
    const float* inp = tens + (size_t)n * (H * W);
    for (int idx = tid; idx < SROWS * (SCOLS + 3); idx += 128) {
        int r  = idx / (SCOLS + 3);
        int c  = idx - r * (SCOLS + 3);
        int gy = y0 - 4 + r;
        int gx = c - 4;
        float v = 0.0f;
        if (gy >= 0 && gy < H && gx >= 0 && gx < W)
            v = inp[gy * W + gx];
        #pragma unroll
        for (int cp = 0; cp < 4; ++cp) {
            int j = c - cp;
            if (j >= 0 && j < SCOLS) s_t[cp][r][j] = v;
        }
    }
    __syncthreads();

    const int ybase = wrp * 4;          // 4 output rows per warp
    const int xo    = 4 * lane;         // 4 output cols per lane
    float* outw = out + (size_t)n * (NS * H * W)
                      + (size_t)(y0 + ybase) * W + xo;

    #pragma unroll 1
    for (int s = 0; s < NS; ++s) {
        const int sy = s_sh[2 * s + 0];
        const int sx = s_sh[2 * s + 1];

        // filter pairs: (f0,f1), (f2,f3), (f4,0) per row — all aligned loads
        u64 fp[5][3];
        #pragma unroll
        for (int i = 0; i < 5; ++i) {
            float4 q = *(const float4*)&s_f[s][i][0];   // f0..f3
            float2 t = *(const float2*)&s_f[s][i][4];   // f4, 0
            fp[i][0] = pk(q.x, q.y);
            fp[i][1] = pk(q.z, q.w);
            fp[i][2] = pk(t.x, t.y);                    // (f4, 0)
        }

        const int rowbase = ybase + 4 - sy;   // [0, 16]
        const int a       = 4 - sx;           // [0, 4]
        const int ce      = a & 3;            // which shifted copy
        const int te      = xo + (a & ~3);    // 16B-aligned window base

        const float* be = &s_t[ce][rowbase][te];

        u64 acc[4][4];
        #pragma unroll
        for (int yy = 0; yy < 4; ++yy)
            #pragma unroll
            for (int d = 0; d < 4; ++d) acc[yy][d] = 0ull;

        #pragma unroll
        for (int k = 0; k < 8; ++k) {
            const float* rp = be + k * SCOLS;
            float4 A = *(const float4*)rp;        // w0..w3 (LDS.128)
            float4 B = *(const float4*)(rp + 4);  // w4..w7 (LDS.128)
            // p[t] = (w_t, w_{t+1}); p7 second half is multiplied by 0 only
            u64 p[8];
            p[0] = pk(A.x, A.y);   // aligned quad halves: no MOVs
            p[2] = pk(A.z, A.w);
            p[4] = pk(B.x, B.y);
            p[6] = pk(B.z, B.w);
            p[1] = pk(A.y, A.z);   // cross pairs: 2 MOVs each
            p[3] = pk(A.w, B.x);
            p[5] = pk(B.y, B.z);
            p[7] = pk(B.w, B.w);   // (w7, dontcare-finite)

            #pragma unroll
            for (int yy = 0; yy < 4; ++yy) {
                const int i = k - yy;             // compile-time after unroll
                if (i >= 0 && i < 5) {
                    #pragma unroll
                    for (int d = 0; d < 4; ++d) {
                        fma2(acc[yy][d], fp[i][0], p[d]);
                        fma2(acc[yy][d], fp[i][1], p[d + 2]);
                        fma2(acc[yy][d], fp[i][2], p[d + 4]);
                    }
                }
            }
        }

        float* ops = outw + (size_t)s * (H * W);
        #pragma unroll
        for (int yy = 0; yy < 4; ++yy) {
            float4 o = make_float4(hadd(acc[yy][0]), hadd(acc[yy][1]),
                                   hadd(acc[yy][2]), hadd(acc[yy][3]));
            *(float4*)(ops + yy * W) = o;         // STG.128
        }
    }
}

extern "C" void kernel_launch(void* const* d_in, const int* in_sizes, int n_in,
                              void* d_out, int out_size)
{
    const float* tens    = (const float*)d_in[0];
    const float* filters = (const float*)d_in[1];
    const int*   shifts  = (const int*)d_in[2];
    float*       out     = (float*)d_out;

    dim3 grid(256, H / TY);   // 2048 blocks
    shifted_conv_kernel<<<grid, 128>>>(tens, filters, shifts, out);
}

// round 11
// speedup vs baseline: 1.2797x; 1.2797x over previous
#include <cuda_runtime.h>
#include <cstdint>

#define H 128
#define W 128
#define NS 8
#define TY 16
#define SROWS (TY + 8)    // 24
#define SCOLS 136         // padded cols: x_pad[c] = x[c-4], c in [0,136)
#define EC    (SCOLS / 2) // 68 entries per parity array row

typedef unsigned long long u64;

__device__ __forceinline__ void fma2(u64& acc, u64 a, u64 b) {
    asm("fma.rn.f32x2 %0, %1, %2, %0;" : "+l"(acc) : "l"(a), "l"(b));
}
__device__ __forceinline__ void unpk(u64 v, float& lo, float& hi) {
    asm("mov.b64 {%0, %1}, %2;" : "=f"(lo), "=f"(hi) : "l"(v));
}

__global__ void __launch_bounds__(128, 5)
shifted_conv_kernel(const float* __restrict__ tens,
                    const float* __restrict__ filters,
                    const int* __restrict__ shifts,
                    float* __restrict__ out)
{
    // Parity-deinterleaved tile, each parity in two copies shifted by one slot:
    //   s_p[p][0][r][i] = x_pad[r][2i+p]
    //   s_p[p][1][r][i] = x_pad[r][2i+p+2]   (= copy0 shifted by one entry)
    __shared__ __align__(16) float s_p[2][2][SROWS][EC];
    __shared__ __align__(16) float2 s_fp[NS][25];   // splatted (f,f) pairs
    __shared__ int s_sh[NS * 2];

    const int n    = blockIdx.x;
    const int y0   = blockIdx.y * TY;
    const int tid  = threadIdx.x;
    const int lane = tid & 31;
    const int wrp  = tid >> 5;

    for (int i = tid; i < NS * 25; i += 128) {
        float f = filters[i];
        s_fp[i / 25][i % 25] = make_float2(f, f);
    }
    if (tid < NS * 2) s_sh[tid] = shifts[tid];

    // Stage: every padded value lands in its parity array (copy0) and the
    // shifted copy (copy1) one slot earlier.
    const float* inp = tens + (size_t)n * (H * W);
    for (int idx = tid; idx < SROWS * SCOLS; idx += 128) {
        int r  = idx / SCOLS;
        int c  = idx - r * SCOLS;
        int gy = y0 - 4 + r;
        int gx = c - 4;
        float v = 0.0f;
        if (gy >= 0 && gy < H && gx >= 0 && gx < W)
            v = inp[gy * W + gx];
        int p = c & 1, i = c >> 1;
        s_p[p][0][r][i] = v;
        if (i > 0) s_p[p][1][r][i - 1] = v;
    }
    for (int r = tid; r < SROWS; r += 128) {   // copy1 tails (x_pad[136/137]=0)
        s_p[0][1][r][EC - 1] = 0.0f;
        s_p[1][1][r][EC - 1] = 0.0f;
    }
    __syncthreads();

    const int ybase = wrp * 4;
    const int xo    = 4 * lane;
    float* outw = out + (size_t)n * (NS * H * W)
                      + (size_t)(y0 + ybase) * W + xo;

    #pragma unroll 1
    for (int s = 0; s < NS; ++s) {
        const int sy = s_sh[2 * s + 0];
        const int sx = s_sh[2 * s + 1];

        // Filter splat pairs: 25 aligned LDS.64, zero MOVs.
        u64 fp[25];
        #pragma unroll
        for (int t = 0; t < 25; ++t) {
            float2 q = s_fp[s][t];
            fp[t] = reinterpret_cast<u64&>(q);
        }

        const int rowbase = ybase + 4 - sy;   // [0,16]
        const int a       = 4 - sx;           // [0,4]
        // Pair t (t=0..5) = (x_pad[c0+t], x_pad[c0+t+2]), c0 = xo + a.
        // Same-parity adjacent entries: parity p_t=(a+t)&1, entry h_t uniform,
        // lane contributes +2l (even) -> copy = h_t&1, index = 2l + h_t - (h_t&1).
        const float* bp[6];
        #pragma unroll
        for (int t = 0; t < 6; ++t) {
            int p = (a + t) & 1;
            int h = (a + t - p) >> 1;
            bp[t] = &s_p[p][h & 1][rowbase][2 * lane + (h & ~1)];
        }

        u64 acc[4][2];                        // [yy][g]: g0=(o0,o2) g1=(o1,o3)
        #pragma unroll
        for (int yy = 0; yy < 4; ++yy) { acc[yy][0] = 0ull; acc[yy][1] = 0ull; }

        #pragma unroll
        for (int k = 0; k < 8; ++k) {
            u64 q[6];
            #pragma unroll
            for (int t = 0; t < 6; ++t) {
                float2 v = *(const float2*)(bp[t] + k * EC);  // aligned LDS.64
                q[t] = reinterpret_cast<u64&>(v);
            }
            #pragma unroll
            for (int yy = 0; yy < 4; ++yy) {
                const int i = k - yy;          // compile-time after unroll
                if (i >= 0 && i < 5) {
                    #pragma unroll
                    for (int j = 0; j < 5; ++j) {
                        fma2(acc[yy][0], fp[i * 5 + j], q[j]);
                        fma2(acc[yy][1], fp[i * 5 + j], q[j + 1]);
                    }
                }
            }
        }

        float* ops = outw + (size_t)s * (H * W);
        #pragma unroll
        for (int yy = 0; yy < 4; ++yy) {
            float o0, o2, o1, o3;
            unpk(acc[yy][0], o0, o2);
            unpk(acc[yy][1], o1, o3);
            *(float4*)(ops + yy * W) = make_float4(o0, o1, o2, o3);
        }
    }
}

extern "C" void kernel_launch(void* const* d_in, const int* in_sizes, int n_in,
                              void* d_out, int out_size)
{
    const float* tens    = (const float*)d_in[0];
    const float* filters = (const float*)d_in[1];
    const int*   shifts  = (const int*)d_in[2];
    float*       out     = (float*)d_out;

    dim3 grid(256, H / TY);
    shifted_conv_kernel<<<grid, 128>>>(tens, filters, shifts, out);
}

// round 12
// speedup vs baseline: 1.3149x; 1.0276x over previous
#include <cuda_runtime.h>
#include <cstdint>

#define H 128
#define W 128
#define NS 8
#define TY 32
#define SROWS (TY + 8)    // 40
#define SCOLS 136         // x_pad[c] = x[c-4], c in [0,136)
#define EC    (SCOLS / 2) // 68 entries per parity row

typedef unsigned long long u64;

__device__ __forceinline__ void fma2(u64& acc, u64 a, u64 b) {
    asm("fma.rn.f32x2 %0, %1, %2, %0;" : "+l"(acc) : "l"(a), "l"(b));
}
__device__ __forceinline__ void mul2(u64& d, u64 a, u64 b) {
    asm("mul.rn.f32x2 %0, %1, %2;" : "=l"(d) : "l"(a), "l"(b));
}
__device__ __forceinline__ void unpk(u64 v, float& lo, float& hi) {
    asm("mov.b64 {%0, %1}, %2;" : "=f"(lo), "=f"(hi) : "l"(v));
}

__global__ void __launch_bounds__(128)
shifted_conv_kernel(const float* __restrict__ tens,
                    const float* __restrict__ filters,
                    const int* __restrict__ shifts,
                    float* __restrict__ out)
{
    // Parity-deinterleaved tile, two copies per parity shifted by one entry:
    //   s_p[p][0][r][i] = x_pad[r][2i+p]
    //   s_p[p][1][r][i] = x_pad[r][2i+p+2]
    __shared__ __align__(16) float s_p[2][2][SROWS][EC];   // 43.5 KB
    __shared__ __align__(16) float2 s_fp[NS][25];          // splatted (f,f)
    __shared__ int s_sh[NS * 2];

    const int n    = blockIdx.x;
    const int y0   = blockIdx.y * TY;   // 0,32,64,96
    const int tid  = threadIdx.x;
    const int lane = tid & 31;
    const int wrp  = tid >> 5;

    for (int i = tid; i < NS * 25; i += 128) {
        float f = filters[i];
        s_fp[i / 25][i % 25] = make_float2(f, f);
    }
    if (tid < NS * 2) s_sh[tid] = shifts[tid];

    const float* inp = tens + (size_t)n * (H * W);
    for (int idx = tid; idx < SROWS * SCOLS; idx += 128) {
        int r  = idx / SCOLS;
        int c  = idx - r * SCOLS;
        int gy = y0 - 4 + r;
        int gx = c - 4;
        float v = 0.0f;
        if (gy >= 0 && gy < H && gx >= 0 && gx < W)
            v = inp[gy * W + gx];
        int p = c & 1, i = c >> 1;
        s_p[p][0][r][i] = v;
        if (i > 0) s_p[p][1][r][i - 1] = v;
    }
    for (int r = tid; r < SROWS; r += 128) {   // copy1 tails: x_pad[136/137]=0
        s_p[0][1][r][EC - 1] = 0.0f;
        s_p[1][1][r][EC - 1] = 0.0f;
    }
    __syncthreads();

    const int ybase = wrp * 8;          // 8 output rows per warp (rotation)
    const int xo    = 4 * lane;         // 4 output cols per lane
    float* outw = out + (size_t)n * (NS * H * W)
                      + (size_t)(y0 + ybase) * W + xo;

    #pragma unroll 1
    for (int s = 0; s < NS; ++s) {
        const int sy = s_sh[2 * s + 0];
        const int sx = s_sh[2 * s + 1];

        // Filter splat pairs: 25 aligned LDS.64, zero MOVs, reused for 8 rows.
        u64 fp[25];
        #pragma unroll
        for (int t = 0; t < 25; ++t) {
            float2 v = s_fp[s][t];
            fp[t] = reinterpret_cast<u64&>(v);
        }

        const int rowbase = ybase + 4 - sy;   // [0, 28]
        const int a       = 4 - sx;           // [0, 4]
        // Pair t = (x_pad[c0+t], x_pad[c0+t+2]), c0 = xo + a. Same-parity
        // adjacent entries; copy选 selects 8B alignment. (Verified R11.)
        const float* bp[6];
        #pragma unroll
        for (int t = 0; t < 6; ++t) {
            int p = (a + t) & 1;
            int h = (a + t - p) >> 1;
            bp[t] = &s_p[p][h & 1][rowbase][2 * lane + (h & ~1)];
        }

        float* ops = outw + (size_t)s * (H * W);

        // Sliding-window over 12 input rows; output row y is live only for
        // k in [y, y+4] (init at i==0, store right after i==4) -> <=5 rows
        // of accumulators live at once.
        u64 acc[8][2];
        #pragma unroll
        for (int k = 0; k < 12; ++k) {
            u64 q[6];
            #pragma unroll
            for (int t = 0; t < 6; ++t) {
                float2 v = *(const float2*)(bp[t] + k * EC);  // aligned LDS.64
                q[t] = reinterpret_cast<u64&>(v);
            }
            #pragma unroll
            for (int y = 0; y < 8; ++y) {
                const int i = k - y;           // compile-time after unroll
                if (i == 0) {
                    mul2(acc[y][0], fp[0], q[0]);
                    mul2(acc[y][1], fp[0], q[1]);
                    #pragma unroll
                    for (int j = 1; j < 5; ++j) {
                        fma2(acc[y][0], fp[j], q[j]);
                        fma2(acc[y][1], fp[j], q[j + 1]);
                    }
                } else if (i >= 1 && i < 5) {
                    #pragma unroll
                    for (int j = 0; j < 5; ++j) {
                        fma2(acc[y][0], fp[i * 5 + j], q[j]);
                        fma2(acc[y][1], fp[i * 5 + j], q[j + 1]);
                    }
                }
            }
            // Row k-4 just received its last tap: store and retire it.
            const int yd = k - 4;
            if (yd >= 0 && yd < 8) {
                float o0, o2, o1, o3;
                unpk(acc[yd][0], o0, o2);
                unpk(acc[yd][1], o1, o3);
                *(float4*)(ops + yd * W) = make_float4(o0, o1, o2, o3);
            }
        }
    }
}

extern "C" void kernel_launch(void* const* d_in, const int* in_sizes, int n_in,
                              void* d_out, int out_size)
{
    const float* tens    = (const float*)d_in[0];
    const float* filters = (const float*)d_in[1];
    const int*   shifts  = (const int*)d_in[2];
    float*       out     = (float*)d_out;

    dim3 grid(256, H / TY);   // (B*C, 4) = 1024 blocks
    shifted_conv_kernel<<<grid, 128>>>(tens, filters, shifts, out);
}